// round 1
// baseline (speedup 1.0000x reference)
#include <cuda_runtime.h>
#include <cuda_bf16.h>
#include <cstdint>

// Problem constants (fixed shapes per reference)
#define NU 200000
#define NI 200000
#define D  64

// ---------------------------------------------------------------------------
// Device scratch (no cudaMalloc allowed)
// ---------------------------------------------------------------------------
__device__ float g_acc_i[(size_t)NI * D];   // 51.2 MB
__device__ float g_acc_u[(size_t)NU * D];   // 51.2 MB
__device__ float g_cnt_i[NI];
__device__ float g_cnt_u[NU];
__device__ float g_h_i[(size_t)NI * D];     // 51.2 MB
__device__ float g_h_u[(size_t)NU * D];     // 51.2 MB

// ---------------------------------------------------------------------------
// Scatter-add: acc[dst] += xsrc[remap ? remap[src] : src]; cnt[dst] += 1
// 16 threads per edge, float4 per thread, vectorized red.global.add.v4.f32
// ---------------------------------------------------------------------------
__global__ void scatter_kernel(const float* __restrict__ xsrc,
                               const int*   __restrict__ remap,
                               const int*   __restrict__ edge,   // [2, E]
                               int E,
                               float* __restrict__ acc,
                               float* __restrict__ cnt)
{
    long long t = (long long)blockIdx.x * blockDim.x + threadIdx.x;
    int e = (int)(t >> 4);
    if (e >= E) return;
    int sub = (int)(t & 15);

    int s = __ldg(edge + e);
    int d = __ldg(edge + E + e);
    if (remap) s = __ldg(remap + s);

    const float4 v = *reinterpret_cast<const float4*>(xsrc + (size_t)s * D + sub * 4);
    float* p = acc + (size_t)d * D + sub * 4;
    asm volatile("red.global.add.v4.f32 [%0], {%1, %2, %3, %4};"
                 :: "l"(p), "f"(v.x), "f"(v.y), "f"(v.z), "f"(v.w)
                 : "memory");
    if (cnt != nullptr && sub == 0) {
        atomicAdd(cnt + d, 1.0f);
    }
}

// ---------------------------------------------------------------------------
// Post: out[r] = L2norm( (acc[r]/max(cnt[r],1)) @ Wl + bl + xdst[r] @ Wr ),
// optional ReLU.  One warp per row; weights staged in shared, pre-packed as
// float2 (cols j and j+32) so each k-step is 2x LDS.64 instead of 4x LDS.32.
// ---------------------------------------------------------------------------
__global__ void __launch_bounds__(256)
sage_post_kernel(const float* __restrict__ acc,
                 const float* __restrict__ cnt,
                 const float* __restrict__ xdst_base,
                 const int*   __restrict__ remap,
                 const float* __restrict__ Wl,
                 const float* __restrict__ bl,
                 const float* __restrict__ Wr,
                 float* __restrict__ out,
                 int N, int relu)
{
    __shared__ float2 sWl[D * 32];
    __shared__ float2 sWr[D * 32];
    __shared__ float  sb[D];

    int tid = threadIdx.x;
    for (int i = tid; i < D * 32; i += blockDim.x) {
        int k = i >> 5, j = i & 31;
        sWl[i] = make_float2(Wl[k * D + j], Wl[k * D + j + 32]);
        sWr[i] = make_float2(Wr[k * D + j], Wr[k * D + j + 32]);
    }
    if (tid < D) sb[tid] = bl[tid];
    __syncthreads();

    int warp = tid >> 5, lane = tid & 31;
    int nwarps = blockDim.x >> 5;

    for (int r = blockIdx.x * nwarps + warp; r < N; r += gridDim.x * nwarps) {
        float c   = cnt[r];
        float inv = 1.0f / fmaxf(c, 1.0f);
        const float* ar = acc + (size_t)r * D;
        float a0 = ar[lane] * inv;
        float a1 = ar[lane + 32] * inv;

        int xr = remap ? remap[r] : r;
        const float* xp = xdst_base + (size_t)xr * D;
        float x0 = xp[lane];
        float x1 = xp[lane + 32];

        float o0 = sb[lane];
        float o1 = sb[lane + 32];

        #pragma unroll
        for (int k = 0; k < 32; k++) {
            float va = __shfl_sync(0xffffffffu, a0, k);
            float vx = __shfl_sync(0xffffffffu, x0, k);
            float2 wl = sWl[k * 32 + lane];
            float2 wr = sWr[k * 32 + lane];
            o0 = fmaf(va, wl.x, o0); o0 = fmaf(vx, wr.x, o0);
            o1 = fmaf(va, wl.y, o1); o1 = fmaf(vx, wr.y, o1);
        }
        #pragma unroll
        for (int k = 0; k < 32; k++) {
            float va = __shfl_sync(0xffffffffu, a1, k);
            float vx = __shfl_sync(0xffffffffu, x1, k);
            float2 wl = sWl[(k + 32) * 32 + lane];
            float2 wr = sWr[(k + 32) * 32 + lane];
            o0 = fmaf(va, wl.x, o0); o0 = fmaf(vx, wr.x, o0);
            o1 = fmaf(va, wl.y, o1); o1 = fmaf(vx, wr.y, o1);
        }

        float ss = o0 * o0 + o1 * o1;
        #pragma unroll
        for (int off = 16; off; off >>= 1)
            ss += __shfl_xor_sync(0xffffffffu, ss, off);
        float nrm = fmaxf(sqrtf(ss), 1e-12f);
        o0 /= nrm;
        o1 /= nrm;
        if (relu) { o0 = fmaxf(o0, 0.0f); o1 = fmaxf(o1, 0.0f); }

        out[(size_t)r * D + lane]      = o0;
        out[(size_t)r * D + lane + 32] = o1;
    }
}

// ---------------------------------------------------------------------------
// Launch
//
// metadata order:
//  0 emb_user  1 emb_item
//  2 W1l_ui 3 b1_ui 4 W1r_ui   5 W1l_iu 6 b1_iu 7 W1r_iu
//  8 W2l_ui 9 b2_ui 10 W2r_ui  11 W2l_iu 12 b2_iu 13 W2r_iu
// 14 n_id_user 15 n_id_item 16 edge_ui 17 edge_iu
// output: concat(o_user [NU*64], o_item [NI*64]) float32
// ---------------------------------------------------------------------------
extern "C" void kernel_launch(void* const* d_in, const int* in_sizes, int n_in,
                              void* d_out, int out_size)
{
    const float* emb_user = (const float*)d_in[0];
    const float* emb_item = (const float*)d_in[1];
    const float* W1l_ui = (const float*)d_in[2];
    const float* b1_ui  = (const float*)d_in[3];
    const float* W1r_ui = (const float*)d_in[4];
    const float* W1l_iu = (const float*)d_in[5];
    const float* b1_iu  = (const float*)d_in[6];
    const float* W1r_iu = (const float*)d_in[7];
    const float* W2l_ui = (const float*)d_in[8];
    const float* b2_ui  = (const float*)d_in[9];
    const float* W2r_ui = (const float*)d_in[10];
    const float* W2l_iu = (const float*)d_in[11];
    const float* b2_iu  = (const float*)d_in[12];
    const float* W2r_iu = (const float*)d_in[13];
    const int* n_id_user = (const int*)d_in[14];
    const int* n_id_item = (const int*)d_in[15];
    const int* edge_ui   = (const int*)d_in[16];
    const int* edge_iu   = (const int*)d_in[17];

    const int E_ui = in_sizes[16] / 2;
    const int E_iu = in_sizes[17] / 2;

    float* out = (float*)d_out;
    float* out_user = out;                     // [NU*64]
    float* out_item = out + (size_t)NU * D;    // [NI*64]

    float *acc_i, *acc_u, *cnt_i, *cnt_u, *h_i, *h_u;
    cudaGetSymbolAddress((void**)&acc_i, g_acc_i);
    cudaGetSymbolAddress((void**)&acc_u, g_acc_u);
    cudaGetSymbolAddress((void**)&cnt_i, g_cnt_i);
    cudaGetSymbolAddress((void**)&cnt_u, g_cnt_u);
    cudaGetSymbolAddress((void**)&h_i, g_h_i);
    cudaGetSymbolAddress((void**)&h_u, g_h_u);

    const size_t accBytesI = (size_t)NI * D * sizeof(float);
    const size_t accBytesU = (size_t)NU * D * sizeof(float);

    const int TPB = 256;
    const int scatterBlocksUI = (int)(((long long)E_ui * 16 + TPB - 1) / TPB);
    const int scatterBlocksIU = (int)(((long long)E_iu * 16 + TPB - 1) / TPB);
    const int postBlocksI = (NI + 7) / 8;   // 8 warps/block, 1 row/warp
    const int postBlocksU = (NU + 7) / 8;

    // ---- Layer 1 ----
    cudaMemsetAsync(acc_i, 0, accBytesI);
    cudaMemsetAsync(acc_u, 0, accBytesU);
    cudaMemsetAsync(cnt_i, 0, NI * sizeof(float));
    cudaMemsetAsync(cnt_u, 0, NU * sizeof(float));

    // h_item: aggregate user -> item over edge_ui
    scatter_kernel<<<scatterBlocksUI, TPB>>>(emb_user, n_id_user, edge_ui, E_ui, acc_i, cnt_i);
    // h_user: aggregate item -> user over edge_iu
    scatter_kernel<<<scatterBlocksIU, TPB>>>(emb_item, n_id_item, edge_iu, E_iu, acc_u, cnt_u);

    sage_post_kernel<<<postBlocksI, TPB>>>(acc_i, cnt_i, emb_item, n_id_item,
                                           W1l_ui, b1_ui, W1r_ui, h_i, NI, 1);
    sage_post_kernel<<<postBlocksU, TPB>>>(acc_u, cnt_u, emb_user, n_id_user,
                                           W1l_iu, b1_iu, W1r_iu, h_u, NU, 1);

    // ---- Layer 2 (counts unchanged — reuse) ----
    cudaMemsetAsync(acc_i, 0, accBytesI);
    cudaMemsetAsync(acc_u, 0, accBytesU);

    scatter_kernel<<<scatterBlocksUI, TPB>>>(h_u, nullptr, edge_ui, E_ui, acc_i, nullptr);
    scatter_kernel<<<scatterBlocksIU, TPB>>>(h_i, nullptr, edge_iu, E_iu, acc_u, nullptr);

    sage_post_kernel<<<postBlocksI, TPB>>>(acc_i, cnt_i, h_i, nullptr,
                                           W2l_ui, b2_ui, W2r_ui, out_item, NI, 0);
    sage_post_kernel<<<postBlocksU, TPB>>>(acc_u, cnt_u, h_u, nullptr,
                                           W2l_iu, b2_iu, W2r_iu, out_user, NU, 0);
}

// round 2
// speedup vs baseline: 1.7683x; 1.7683x over previous
#include <cuda_runtime.h>
#include <cuda_bf16.h>
#include <cstdint>

// Problem constants (fixed shapes per reference)
#define NU 200000
#define NI 200000
#define D  64

// ---------------------------------------------------------------------------
// Device scratch (no cudaMalloc allowed)
// ---------------------------------------------------------------------------
__device__ float g_acc_i[(size_t)NI * D];   // 51.2 MB
__device__ float g_acc_u[(size_t)NU * D];   // 51.2 MB
__device__ float g_cnt_i[NI];
__device__ float g_cnt_u[NU];
__device__ float g_h_i[(size_t)NI * D];     // 51.2 MB
__device__ float g_h_u[(size_t)NU * D];     // 51.2 MB

// ---------------------------------------------------------------------------
// Scatter-add: acc[dst] += xsrc[remap ? remap[src] : src]; cnt[dst] += 1
// 16 threads per edge, float4 per thread, vectorized red.global.add.v4.f32
// ---------------------------------------------------------------------------
__global__ void scatter_kernel(const float* __restrict__ xsrc,
                               const int*   __restrict__ remap,
                               const int*   __restrict__ edge,   // [2, E]
                               int E,
                               float* __restrict__ acc,
                               float* __restrict__ cnt)
{
    long long t = (long long)blockIdx.x * blockDim.x + threadIdx.x;
    int e = (int)(t >> 4);
    if (e >= E) return;
    int sub = (int)(t & 15);

    int s = __ldg(edge + e);
    int d = __ldg(edge + E + e);
    if (remap) s = __ldg(remap + s);

    const float4 v = *reinterpret_cast<const float4*>(xsrc + (size_t)s * D + sub * 4);
    float* p = acc + (size_t)d * D + sub * 4;
    asm volatile("red.global.add.v4.f32 [%0], {%1, %2, %3, %4};"
                 :: "l"(p), "f"(v.x), "f"(v.y), "f"(v.z), "f"(v.w)
                 : "memory");
    if (cnt != nullptr && sub == 0) {
        atomicAdd(cnt + d, 1.0f);
    }
}

// ---------------------------------------------------------------------------
// Post as register-tiled GEMM:
//   out[64-row tile, 64 cols] = L2norm_rows( [agg | x] (64x128) @ [Wl;Wr] (128x64) + b )
// Block: 256 threads as (tx,ty) in 16x16. Each thread: 4 rows x 4 cols.
// Shared: input tile k-major [128][64] (pitch 68 floats, f4-aligned,
// conflict-free), weights [128][64] same pitch. Per k-step: 2x LDS.128
// feeding 16 FMAs.
// ---------------------------------------------------------------------------
#define PITCH 68

__global__ void __launch_bounds__(256)
sage_post_gemm(const float* __restrict__ acc,
               const float* __restrict__ cnt,
               const float* __restrict__ xdst_base,
               const int*   __restrict__ remap,
               const float* __restrict__ Wl,
               const float* __restrict__ bl,
               const float* __restrict__ Wr,
               float* __restrict__ out,
               int N, int relu)
{
    __shared__ float sIn[128 * PITCH];  // sIn[k][r]
    __shared__ float sW [128 * PITCH];  // sW[k][c]

    const int tid = threadIdx.x;
    const int r0 = blockIdx.x * 64;

    // ---- Stage weights: sW[k][c] = Wl[k][c] (k<64) | Wr[k-64][c] ----
    // 8192 floats = 2048 float4; 8 f4 per thread.
    #pragma unroll
    for (int p = 0; p < 8; p++) {
        int i = tid + p * 256;          // f4 index 0..2047
        int k = i >> 4;                 // 0..127
        int c = (i & 15) << 2;          // 0..60
        float4 w = (k < 64)
            ? *reinterpret_cast<const float4*>(Wl + k * D + c)
            : *reinterpret_cast<const float4*>(Wr + (k - 64) * D + c);
        *reinterpret_cast<float4*>(&sW[k * PITCH + c]) = w;
    }

    // ---- Stage input tile (transposed to k-major) ----
    // row = tid & 63 (32 consecutive rows per warp -> conflict-free STS),
    // q = tid >> 6 selects a 16-k chunk.
    {
        int row = tid & 63;
        int q   = tid >> 6;             // 0..3
        int gr  = r0 + row;
        bool ok = (gr < N);
        float inv = 1.0f;
        const float* ap = acc;
        const float* xp = xdst_base;
        if (ok) {
            inv = 1.0f / fmaxf(cnt[gr], 1.0f);
            ap = acc + (size_t)gr * D;
            int xr = remap ? __ldg(remap + gr) : gr;
            xp = xdst_base + (size_t)xr * D;
        }
        #pragma unroll
        for (int j = 0; j < 4; j++) {
            int k = q * 16 + j * 4;     // 0..63
            float4 va = ok ? *reinterpret_cast<const float4*>(ap + k) : make_float4(0,0,0,0);
            sIn[(k + 0) * PITCH + row] = va.x * inv;
            sIn[(k + 1) * PITCH + row] = va.y * inv;
            sIn[(k + 2) * PITCH + row] = va.z * inv;
            sIn[(k + 3) * PITCH + row] = va.w * inv;
            float4 vx = ok ? *reinterpret_cast<const float4*>(xp + k) : make_float4(0,0,0,0);
            sIn[(64 + k + 0) * PITCH + row] = vx.x;
            sIn[(64 + k + 1) * PITCH + row] = vx.y;
            sIn[(64 + k + 2) * PITCH + row] = vx.z;
            sIn[(64 + k + 3) * PITCH + row] = vx.w;
        }
    }
    __syncthreads();

    const int tx = tid & 15;            // col group
    const int ty = tid >> 4;            // row group

    // Accumulators init with bias (same bias for all 4 rows)
    float4 b4 = *reinterpret_cast<const float4*>(bl + tx * 4);
    float o[4][4];
    #pragma unroll
    for (int rr = 0; rr < 4; rr++) {
        o[rr][0] = b4.x; o[rr][1] = b4.y; o[rr][2] = b4.z; o[rr][3] = b4.w;
    }

    // ---- Main GEMM loop: 128 k-steps ----
    #pragma unroll 8
    for (int k = 0; k < 128; k++) {
        float4 a = *reinterpret_cast<const float4*>(&sIn[k * PITCH + ty * 4]);
        float4 w = *reinterpret_cast<const float4*>(&sW [k * PITCH + tx * 4]);
        o[0][0] = fmaf(a.x, w.x, o[0][0]); o[0][1] = fmaf(a.x, w.y, o[0][1]);
        o[0][2] = fmaf(a.x, w.z, o[0][2]); o[0][3] = fmaf(a.x, w.w, o[0][3]);
        o[1][0] = fmaf(a.y, w.x, o[1][0]); o[1][1] = fmaf(a.y, w.y, o[1][1]);
        o[1][2] = fmaf(a.y, w.z, o[1][2]); o[1][3] = fmaf(a.y, w.w, o[1][3]);
        o[2][0] = fmaf(a.z, w.x, o[2][0]); o[2][1] = fmaf(a.z, w.y, o[2][1]);
        o[2][2] = fmaf(a.z, w.z, o[2][2]); o[2][3] = fmaf(a.z, w.w, o[2][3]);
        o[3][0] = fmaf(a.w, w.x, o[3][0]); o[3][1] = fmaf(a.w, w.y, o[3][1]);
        o[3][2] = fmaf(a.w, w.z, o[3][2]); o[3][3] = fmaf(a.w, w.w, o[3][3]);
    }

    // ---- Row-wise L2 norm across the 16 tx threads (lane bits 0..3) ----
    float ss[4];
    #pragma unroll
    for (int rr = 0; rr < 4; rr++) {
        ss[rr] = o[rr][0]*o[rr][0] + o[rr][1]*o[rr][1]
               + o[rr][2]*o[rr][2] + o[rr][3]*o[rr][3];
    }
    #pragma unroll
    for (int m = 1; m <= 8; m <<= 1) {
        #pragma unroll
        for (int rr = 0; rr < 4; rr++)
            ss[rr] += __shfl_xor_sync(0xffffffffu, ss[rr], m);
    }

    #pragma unroll
    for (int rr = 0; rr < 4; rr++) {
        int gr = r0 + ty * 4 + rr;
        if (gr >= N) continue;
        float invn = 1.0f / fmaxf(sqrtf(ss[rr]), 1e-12f);
        float4 v;
        v.x = o[rr][0] * invn; v.y = o[rr][1] * invn;
        v.z = o[rr][2] * invn; v.w = o[rr][3] * invn;
        if (relu) {
            v.x = fmaxf(v.x, 0.0f); v.y = fmaxf(v.y, 0.0f);
            v.z = fmaxf(v.z, 0.0f); v.w = fmaxf(v.w, 0.0f);
        }
        *reinterpret_cast<float4*>(out + (size_t)gr * D + tx * 4) = v;
    }
}

// ---------------------------------------------------------------------------
// Launch
//
// metadata order:
//  0 emb_user  1 emb_item
//  2 W1l_ui 3 b1_ui 4 W1r_ui   5 W1l_iu 6 b1_iu 7 W1r_iu
//  8 W2l_ui 9 b2_ui 10 W2r_ui  11 W2l_iu 12 b2_iu 13 W2r_iu
// 14 n_id_user 15 n_id_item 16 edge_ui 17 edge_iu
// output: concat(o_user [NU*64], o_item [NI*64]) float32
// ---------------------------------------------------------------------------
extern "C" void kernel_launch(void* const* d_in, const int* in_sizes, int n_in,
                              void* d_out, int out_size)
{
    const float* emb_user = (const float*)d_in[0];
    const float* emb_item = (const float*)d_in[1];
    const float* W1l_ui = (const float*)d_in[2];
    const float* b1_ui  = (const float*)d_in[3];
    const float* W1r_ui = (const float*)d_in[4];
    const float* W1l_iu = (const float*)d_in[5];
    const float* b1_iu  = (const float*)d_in[6];
    const float* W1r_iu = (const float*)d_in[7];
    const float* W2l_ui = (const float*)d_in[8];
    const float* b2_ui  = (const float*)d_in[9];
    const float* W2r_ui = (const float*)d_in[10];
    const float* W2l_iu = (const float*)d_in[11];
    const float* b2_iu  = (const float*)d_in[12];
    const float* W2r_iu = (const float*)d_in[13];
    const int* n_id_user = (const int*)d_in[14];
    const int* n_id_item = (const int*)d_in[15];
    const int* edge_ui   = (const int*)d_in[16];
    const int* edge_iu   = (const int*)d_in[17];

    const int E_ui = in_sizes[16] / 2;
    const int E_iu = in_sizes[17] / 2;

    float* out = (float*)d_out;
    float* out_user = out;                     // [NU*64]
    float* out_item = out + (size_t)NU * D;    // [NI*64]

    float *acc_i, *acc_u, *cnt_i, *cnt_u, *h_i, *h_u;
    cudaGetSymbolAddress((void**)&acc_i, g_acc_i);
    cudaGetSymbolAddress((void**)&acc_u, g_acc_u);
    cudaGetSymbolAddress((void**)&cnt_i, g_cnt_i);
    cudaGetSymbolAddress((void**)&cnt_u, g_cnt_u);
    cudaGetSymbolAddress((void**)&h_i, g_h_i);
    cudaGetSymbolAddress((void**)&h_u, g_h_u);

    const size_t accBytesI = (size_t)NI * D * sizeof(float);
    const size_t accBytesU = (size_t)NU * D * sizeof(float);

    const int TPB = 256;
    const int scatterBlocksUI = (int)(((long long)E_ui * 16 + TPB - 1) / TPB);
    const int scatterBlocksIU = (int)(((long long)E_iu * 16 + TPB - 1) / TPB);
    const int postBlocksI = (NI + 63) / 64;
    const int postBlocksU = (NU + 63) / 64;

    // ---- Layer 1 ----
    cudaMemsetAsync(acc_i, 0, accBytesI);
    cudaMemsetAsync(acc_u, 0, accBytesU);
    cudaMemsetAsync(cnt_i, 0, NI * sizeof(float));
    cudaMemsetAsync(cnt_u, 0, NU * sizeof(float));

    // h_item: aggregate user -> item over edge_ui
    scatter_kernel<<<scatterBlocksUI, TPB>>>(emb_user, n_id_user, edge_ui, E_ui, acc_i, cnt_i);
    // h_user: aggregate item -> user over edge_iu
    scatter_kernel<<<scatterBlocksIU, TPB>>>(emb_item, n_id_item, edge_iu, E_iu, acc_u, cnt_u);

    sage_post_gemm<<<postBlocksI, TPB>>>(acc_i, cnt_i, emb_item, n_id_item,
                                         W1l_ui, b1_ui, W1r_ui, h_i, NI, 1);
    sage_post_gemm<<<postBlocksU, TPB>>>(acc_u, cnt_u, emb_user, n_id_user,
                                         W1l_iu, b1_iu, W1r_iu, h_u, NU, 1);

    // ---- Layer 2 (counts unchanged — reuse) ----
    cudaMemsetAsync(acc_i, 0, accBytesI);
    cudaMemsetAsync(acc_u, 0, accBytesU);

    scatter_kernel<<<scatterBlocksUI, TPB>>>(h_u, nullptr, edge_ui, E_ui, acc_i, nullptr);
    scatter_kernel<<<scatterBlocksIU, TPB>>>(h_i, nullptr, edge_iu, E_iu, acc_u, nullptr);

    sage_post_gemm<<<postBlocksI, TPB>>>(acc_i, cnt_i, h_i, nullptr,
                                         W2l_ui, b2_ui, W2r_ui, out_item, NI, 0);
    sage_post_gemm<<<postBlocksU, TPB>>>(acc_u, cnt_u, h_u, nullptr,
                                         W2l_iu, b2_iu, W2r_iu, out_user, NU, 0);
}

// round 3
// speedup vs baseline: 2.3999x; 1.3572x over previous
#include <cuda_runtime.h>
#include <cuda_bf16.h>
#include <cstdint>

#define NU 200000
#define NI 200000
#define D  64
#define MAXE 2000000
#define NB_I ((NI + 255) / 256)
#define NB_U ((NU + 255) / 256)

// ---------------------------------------------------------------------------
// Device scratch (no cudaMalloc allowed)
// ---------------------------------------------------------------------------
__device__ float g_acc_i[(size_t)NI * D];   // mean-aggregated features
__device__ float g_acc_u[(size_t)NU * D];
__device__ float g_h_i[(size_t)NI * D];
__device__ float g_h_u[(size_t)NU * D];
__device__ int g_deg_i[NI];
__device__ int g_deg_u[NU];
__device__ int g_rp_i[NI + 1];
__device__ int g_rp_u[NU + 1];
__device__ int g_cur_i[NI];
__device__ int g_cur_u[NU];
__device__ int g_perm_ui[MAXE];
__device__ int g_perm_iu[MAXE];
__device__ int g_bsum[1024];
__device__ int g_boff[1024];

// ---------------------------------------------------------------------------
// CSR build
// ---------------------------------------------------------------------------
__global__ void hist_k(const int* __restrict__ dst, int E, int* __restrict__ deg)
{
    int i = blockIdx.x * blockDim.x + threadIdx.x;
    if (i < E) atomicAdd(&deg[__ldg(dst + i)], 1);
}

__global__ void scanA_k(const int* __restrict__ deg, int N, int* __restrict__ bsum)
{
    __shared__ int s[256];
    int tid = threadIdx.x;
    int i = blockIdx.x * 256 + tid;
    s[tid] = (i < N) ? deg[i] : 0;
    __syncthreads();
    #pragma unroll
    for (int o = 128; o; o >>= 1) {
        if (tid < o) s[tid] += s[tid + o];
        __syncthreads();
    }
    if (tid == 0) bsum[blockIdx.x] = s[0];
}

__global__ void scanB_k(const int* __restrict__ bsum, int NB,
                        int* __restrict__ boff, int* __restrict__ rowptr, int N)
{
    __shared__ int s[1024];
    int tid = threadIdx.x;
    int v = (tid < NB) ? bsum[tid] : 0;
    s[tid] = v;
    __syncthreads();
    for (int o = 1; o < 1024; o <<= 1) {
        int t = (tid >= o) ? s[tid - o] : 0;
        __syncthreads();
        s[tid] += t;
        __syncthreads();
    }
    if (tid < NB) boff[tid] = s[tid] - v;       // exclusive
    if (tid == NB - 1) rowptr[N] = s[tid];      // total = E
}

__global__ void scanC_k(const int* __restrict__ deg, int N,
                        const int* __restrict__ boff,
                        int* __restrict__ rowptr, int* __restrict__ cursor)
{
    __shared__ int s[256];
    int tid = threadIdx.x;
    int i = blockIdx.x * 256 + tid;
    int v = (i < N) ? deg[i] : 0;
    s[tid] = v;
    __syncthreads();
    #pragma unroll
    for (int o = 1; o < 256; o <<= 1) {
        int t = (tid >= o) ? s[tid - o] : 0;
        __syncthreads();
        s[tid] += t;
        __syncthreads();
    }
    if (i < N) {
        int ex = boff[blockIdx.x] + s[tid] - v;
        rowptr[i] = ex;
        cursor[i] = ex;
    }
}

__global__ void permute_k(const int* __restrict__ edge, int E,
                          int* __restrict__ cursor, int* __restrict__ perm)
{
    int i = blockIdx.x * blockDim.x + threadIdx.x;
    if (i < E) {
        int s = __ldg(edge + i);
        int d = __ldg(edge + E + i);
        int slot = atomicAdd(&cursor[d], 1);
        perm[slot] = s;
    }
}

// ---------------------------------------------------------------------------
// Gather-side aggregation (mean). One warp per dst row. Neighbor indices are
// batch-loaded coalesced (32 per LDG pass), distributed via shfl, so the
// 256B row gathers are independent -> high MLP, no atomics.
// ---------------------------------------------------------------------------
__global__ void __launch_bounds__(256)
agg_k(const float* __restrict__ xsrc,
      const int*   __restrict__ remap,
      const int*   __restrict__ rowptr,
      const int*   __restrict__ perm,
      float* __restrict__ outm,
      int N)
{
    int w = (blockIdx.x * blockDim.x + threadIdx.x) >> 5;
    int lane = threadIdx.x & 31;
    if (w >= N) return;

    int start = __ldg(rowptr + w);
    int end   = __ldg(rowptr + w + 1);

    float ax = 0.0f, ay = 0.0f;
    for (int base = start; base < end; base += 32) {
        int rem = end - base;
        int idx = 0;
        if (lane < rem) {
            idx = __ldg(perm + base + lane);
            if (remap) idx = __ldg(remap + idx);
        }
        int m = rem < 32 ? rem : 32;
        for (int j = 0; j < m; j++) {
            int s2 = __shfl_sync(0xffffffffu, idx, j);
            float2 v = *reinterpret_cast<const float2*>(xsrc + (size_t)s2 * D + lane * 2);
            ax += v.x;
            ay += v.y;
        }
    }

    int deg = end - start;
    float inv = (deg > 0) ? (1.0f / (float)deg) : 0.0f;
    float2 o;
    o.x = ax * inv;
    o.y = ay * inv;
    *reinterpret_cast<float2*>(outm + (size_t)w * D + lane * 2) = o;
}

// ---------------------------------------------------------------------------
// Post as register-tiled GEMM (acc already holds the mean):
//   out[64-row tile] = L2norm_rows( [agg | x] (64x128) @ [Wl;Wr] (128x64) + b )
// ---------------------------------------------------------------------------
#define PITCH 68

__global__ void __launch_bounds__(256)
sage_post_gemm(const float* __restrict__ acc,
               const float* __restrict__ xdst_base,
               const int*   __restrict__ remap,
               const float* __restrict__ Wl,
               const float* __restrict__ bl,
               const float* __restrict__ Wr,
               float* __restrict__ out,
               int N, int relu)
{
    __shared__ float sIn[128 * PITCH];  // sIn[k][r]
    __shared__ float sW [128 * PITCH];  // sW[k][c]

    const int tid = threadIdx.x;
    const int r0 = blockIdx.x * 64;

    #pragma unroll
    for (int p = 0; p < 8; p++) {
        int i = tid + p * 256;
        int k = i >> 4;
        int c = (i & 15) << 2;
        float4 w = (k < 64)
            ? *reinterpret_cast<const float4*>(Wl + k * D + c)
            : *reinterpret_cast<const float4*>(Wr + (k - 64) * D + c);
        *reinterpret_cast<float4*>(&sW[k * PITCH + c]) = w;
    }

    {
        int row = tid & 63;
        int q   = tid >> 6;
        int gr  = r0 + row;
        bool ok = (gr < N);
        const float* ap = acc;
        const float* xp = xdst_base;
        if (ok) {
            ap = acc + (size_t)gr * D;
            int xr = remap ? __ldg(remap + gr) : gr;
            xp = xdst_base + (size_t)xr * D;
        }
        #pragma unroll
        for (int j = 0; j < 4; j++) {
            int k = q * 16 + j * 4;
            float4 va = ok ? *reinterpret_cast<const float4*>(ap + k) : make_float4(0,0,0,0);
            sIn[(k + 0) * PITCH + row] = va.x;
            sIn[(k + 1) * PITCH + row] = va.y;
            sIn[(k + 2) * PITCH + row] = va.z;
            sIn[(k + 3) * PITCH + row] = va.w;
            float4 vx = ok ? *reinterpret_cast<const float4*>(xp + k) : make_float4(0,0,0,0);
            sIn[(64 + k + 0) * PITCH + row] = vx.x;
            sIn[(64 + k + 1) * PITCH + row] = vx.y;
            sIn[(64 + k + 2) * PITCH + row] = vx.z;
            sIn[(64 + k + 3) * PITCH + row] = vx.w;
        }
    }
    __syncthreads();

    const int tx = tid & 15;
    const int ty = tid >> 4;

    float4 b4 = *reinterpret_cast<const float4*>(bl + tx * 4);
    float o[4][4];
    #pragma unroll
    for (int rr = 0; rr < 4; rr++) {
        o[rr][0] = b4.x; o[rr][1] = b4.y; o[rr][2] = b4.z; o[rr][3] = b4.w;
    }

    #pragma unroll 8
    for (int k = 0; k < 128; k++) {
        float4 a = *reinterpret_cast<const float4*>(&sIn[k * PITCH + ty * 4]);
        float4 w = *reinterpret_cast<const float4*>(&sW [k * PITCH + tx * 4]);
        o[0][0] = fmaf(a.x, w.x, o[0][0]); o[0][1] = fmaf(a.x, w.y, o[0][1]);
        o[0][2] = fmaf(a.x, w.z, o[0][2]); o[0][3] = fmaf(a.x, w.w, o[0][3]);
        o[1][0] = fmaf(a.y, w.x, o[1][0]); o[1][1] = fmaf(a.y, w.y, o[1][1]);
        o[1][2] = fmaf(a.y, w.z, o[1][2]); o[1][3] = fmaf(a.y, w.w, o[1][3]);
        o[2][0] = fmaf(a.z, w.x, o[2][0]); o[2][1] = fmaf(a.z, w.y, o[2][1]);
        o[2][2] = fmaf(a.z, w.z, o[2][2]); o[2][3] = fmaf(a.z, w.w, o[2][3]);
        o[3][0] = fmaf(a.w, w.x, o[3][0]); o[3][1] = fmaf(a.w, w.y, o[3][1]);
        o[3][2] = fmaf(a.w, w.z, o[3][2]); o[3][3] = fmaf(a.w, w.w, o[3][3]);
    }

    float ss[4];
    #pragma unroll
    for (int rr = 0; rr < 4; rr++) {
        ss[rr] = o[rr][0]*o[rr][0] + o[rr][1]*o[rr][1]
               + o[rr][2]*o[rr][2] + o[rr][3]*o[rr][3];
    }
    #pragma unroll
    for (int m = 1; m <= 8; m <<= 1) {
        #pragma unroll
        for (int rr = 0; rr < 4; rr++)
            ss[rr] += __shfl_xor_sync(0xffffffffu, ss[rr], m);
    }

    #pragma unroll
    for (int rr = 0; rr < 4; rr++) {
        int gr = r0 + ty * 4 + rr;
        if (gr >= N) continue;
        float invn = 1.0f / fmaxf(sqrtf(ss[rr]), 1e-12f);
        float4 v;
        v.x = o[rr][0] * invn; v.y = o[rr][1] * invn;
        v.z = o[rr][2] * invn; v.w = o[rr][3] * invn;
        if (relu) {
            v.x = fmaxf(v.x, 0.0f); v.y = fmaxf(v.y, 0.0f);
            v.z = fmaxf(v.z, 0.0f); v.w = fmaxf(v.w, 0.0f);
        }
        *reinterpret_cast<float4*>(out + (size_t)gr * D + tx * 4) = v;
    }
}

// ---------------------------------------------------------------------------
// Launch
// ---------------------------------------------------------------------------
extern "C" void kernel_launch(void* const* d_in, const int* in_sizes, int n_in,
                              void* d_out, int out_size)
{
    const float* emb_user = (const float*)d_in[0];
    const float* emb_item = (const float*)d_in[1];
    const float* W1l_ui = (const float*)d_in[2];
    const float* b1_ui  = (const float*)d_in[3];
    const float* W1r_ui = (const float*)d_in[4];
    const float* W1l_iu = (const float*)d_in[5];
    const float* b1_iu  = (const float*)d_in[6];
    const float* W1r_iu = (const float*)d_in[7];
    const float* W2l_ui = (const float*)d_in[8];
    const float* b2_ui  = (const float*)d_in[9];
    const float* W2r_ui = (const float*)d_in[10];
    const float* W2l_iu = (const float*)d_in[11];
    const float* b2_iu  = (const float*)d_in[12];
    const float* W2r_iu = (const float*)d_in[13];
    const int* n_id_user = (const int*)d_in[14];
    const int* n_id_item = (const int*)d_in[15];
    const int* edge_ui   = (const int*)d_in[16];
    const int* edge_iu   = (const int*)d_in[17];

    const int E_ui = in_sizes[16] / 2;
    const int E_iu = in_sizes[17] / 2;

    float* out = (float*)d_out;
    float* out_user = out;                     // [NU*64]
    float* out_item = out + (size_t)NU * D;    // [NI*64]

    float *acc_i, *acc_u, *h_i, *h_u;
    int *deg_i, *deg_u, *rp_i, *rp_u, *cur_i, *cur_u, *perm_ui, *perm_iu, *bsum, *boff;
    cudaGetSymbolAddress((void**)&acc_i, g_acc_i);
    cudaGetSymbolAddress((void**)&acc_u, g_acc_u);
    cudaGetSymbolAddress((void**)&h_i, g_h_i);
    cudaGetSymbolAddress((void**)&h_u, g_h_u);
    cudaGetSymbolAddress((void**)&deg_i, g_deg_i);
    cudaGetSymbolAddress((void**)&deg_u, g_deg_u);
    cudaGetSymbolAddress((void**)&rp_i, g_rp_i);
    cudaGetSymbolAddress((void**)&rp_u, g_rp_u);
    cudaGetSymbolAddress((void**)&cur_i, g_cur_i);
    cudaGetSymbolAddress((void**)&cur_u, g_cur_u);
    cudaGetSymbolAddress((void**)&perm_ui, g_perm_ui);
    cudaGetSymbolAddress((void**)&perm_iu, g_perm_iu);
    cudaGetSymbolAddress((void**)&bsum, g_bsum);
    cudaGetSymbolAddress((void**)&boff, g_boff);

    const int TPB = 256;
    const int eBlocksUI = (E_ui + TPB - 1) / TPB;
    const int eBlocksIU = (E_iu + TPB - 1) / TPB;
    const int aggBlocksI = (NI * 32 + TPB - 1) / TPB;   // one warp per row
    const int aggBlocksU = (NU * 32 + TPB - 1) / TPB;
    const int postBlocksI = (NI + 63) / 64;
    const int postBlocksU = (NU + 63) / 64;

    // ---- CSR build (item side: edge_ui dst; user side: edge_iu dst) ----
    cudaMemsetAsync(deg_i, 0, NI * sizeof(int));
    cudaMemsetAsync(deg_u, 0, NU * sizeof(int));

    hist_k<<<eBlocksUI, TPB>>>(edge_ui + E_ui, E_ui, deg_i);
    hist_k<<<eBlocksIU, TPB>>>(edge_iu + E_iu, E_iu, deg_u);

    scanA_k<<<NB_I, 256>>>(deg_i, NI, bsum);
    scanB_k<<<1, 1024>>>(bsum, NB_I, boff, rp_i, NI);
    scanC_k<<<NB_I, 256>>>(deg_i, NI, boff, rp_i, cur_i);
    permute_k<<<eBlocksUI, TPB>>>(edge_ui, E_ui, cur_i, perm_ui);

    scanA_k<<<NB_U, 256>>>(deg_u, NU, bsum);
    scanB_k<<<1, 1024>>>(bsum, NB_U, boff, rp_u, NU);
    scanC_k<<<NB_U, 256>>>(deg_u, NU, boff, rp_u, cur_u);
    permute_k<<<eBlocksIU, TPB>>>(edge_iu, E_iu, cur_u, perm_iu);

    // ---- Layer 1 ----
    agg_k<<<aggBlocksI, TPB>>>(emb_user, n_id_user, rp_i, perm_ui, acc_i, NI);
    agg_k<<<aggBlocksU, TPB>>>(emb_item, n_id_item, rp_u, perm_iu, acc_u, NU);

    sage_post_gemm<<<postBlocksI, TPB>>>(acc_i, emb_item, n_id_item,
                                         W1l_ui, b1_ui, W1r_ui, h_i, NI, 1);
    sage_post_gemm<<<postBlocksU, TPB>>>(acc_u, emb_user, n_id_user,
                                         W1l_iu, b1_iu, W1r_iu, h_u, NU, 1);

    // ---- Layer 2 (same CSR) ----
    agg_k<<<aggBlocksI, TPB>>>(h_u, nullptr, rp_i, perm_ui, acc_i, NI);
    agg_k<<<aggBlocksU, TPB>>>(h_i, nullptr, rp_u, perm_iu, acc_u, NU);

    sage_post_gemm<<<postBlocksI, TPB>>>(acc_i, h_i, nullptr,
                                         W2l_ui, b2_ui, W2r_ui, out_item, NI, 0);
    sage_post_gemm<<<postBlocksU, TPB>>>(acc_u, h_u, nullptr,
                                         W2l_iu, b2_iu, W2r_iu, out_user, NU, 0);
}

// round 4
// speedup vs baseline: 2.4849x; 1.0354x over previous
#include <cuda_runtime.h>
#include <cuda_bf16.h>
#include <cstdint>

#define NU 200000
#define NI 200000
#define D  64
#define MAXE 2000000
#define NB_I ((NI + 255) / 256)
#define NB_U ((NU + 255) / 256)

// ---------------------------------------------------------------------------
// Device scratch (no cudaMalloc allowed)
// ---------------------------------------------------------------------------
__device__ float g_acc_i[(size_t)NI * D];
__device__ float g_acc_u[(size_t)NU * D];
__device__ float g_h_i[(size_t)NI * D];
__device__ float g_h_u[(size_t)NU * D];
__device__ int g_deg_i[NI];
__device__ int g_deg_u[NU];
__device__ int g_rp_i[NI + 1];
__device__ int g_rp_u[NU + 1];
__device__ int g_cur_i[NI];
__device__ int g_cur_u[NU];
__device__ int g_perm_ui[MAXE];
__device__ int g_perm_iu[MAXE];
__device__ int g_bsum[1024];
__device__ int g_boff[1024];

// packed f32x2 helpers
#define PACK2(r, x, y) asm("mov.b64 %0, {%1, %2};" : "=l"(r) : "f"(x), "f"(y))
#define UNPACK2(x, y, r) asm("mov.b64 {%0, %1}, %2;" : "=f"(x), "=f"(y) : "l"(r))
#define FMA2(acc, a, b) asm("fma.rn.f32x2 %0, %1, %2, %0;" : "+l"(acc) : "l"(a), "l"(b))

// ---------------------------------------------------------------------------
// CSR build
// ---------------------------------------------------------------------------
__global__ void hist_k(const int* __restrict__ dst, int E, int* __restrict__ deg)
{
    int i = blockIdx.x * blockDim.x + threadIdx.x;
    if (i < E) atomicAdd(&deg[__ldg(dst + i)], 1);
}

__global__ void scanA_k(const int* __restrict__ deg, int N, int* __restrict__ bsum)
{
    __shared__ int s[256];
    int tid = threadIdx.x;
    int i = blockIdx.x * 256 + tid;
    s[tid] = (i < N) ? deg[i] : 0;
    __syncthreads();
    #pragma unroll
    for (int o = 128; o; o >>= 1) {
        if (tid < o) s[tid] += s[tid + o];
        __syncthreads();
    }
    if (tid == 0) bsum[blockIdx.x] = s[0];
}

__global__ void scanB_k(const int* __restrict__ bsum, int NB,
                        int* __restrict__ boff, int* __restrict__ rowptr, int N)
{
    __shared__ int s[1024];
    int tid = threadIdx.x;
    int v = (tid < NB) ? bsum[tid] : 0;
    s[tid] = v;
    __syncthreads();
    for (int o = 1; o < 1024; o <<= 1) {
        int t = (tid >= o) ? s[tid - o] : 0;
        __syncthreads();
        s[tid] += t;
        __syncthreads();
    }
    if (tid < NB) boff[tid] = s[tid] - v;
    if (tid == NB - 1) rowptr[N] = s[tid];
}

__global__ void scanC_k(const int* __restrict__ deg, int N,
                        const int* __restrict__ boff,
                        int* __restrict__ rowptr, int* __restrict__ cursor)
{
    __shared__ int s[256];
    int tid = threadIdx.x;
    int i = blockIdx.x * 256 + tid;
    int v = (i < N) ? deg[i] : 0;
    s[tid] = v;
    __syncthreads();
    #pragma unroll
    for (int o = 1; o < 256; o <<= 1) {
        int t = (tid >= o) ? s[tid - o] : 0;
        __syncthreads();
        s[tid] += t;
        __syncthreads();
    }
    if (i < N) {
        int ex = boff[blockIdx.x] + s[tid] - v;
        rowptr[i] = ex;
        cursor[i] = ex;
    }
}

__global__ void permute_k(const int* __restrict__ edge, int E,
                          int* __restrict__ cursor, int* __restrict__ perm)
{
    int i = blockIdx.x * blockDim.x + threadIdx.x;
    if (i < E) {
        int s = __ldg(edge + i);
        int d = __ldg(edge + E + i);
        int slot = atomicAdd(&cursor[d], 1);
        perm[slot] = s;
    }
}

// ---------------------------------------------------------------------------
// Gather-side aggregation (mean). One warp per dst row.
// ---------------------------------------------------------------------------
__global__ void __launch_bounds__(256)
agg_k(const float* __restrict__ xsrc,
      const int*   __restrict__ remap,
      const int*   __restrict__ rowptr,
      const int*   __restrict__ perm,
      float* __restrict__ outm,
      int N)
{
    int w = (blockIdx.x * blockDim.x + threadIdx.x) >> 5;
    int lane = threadIdx.x & 31;
    if (w >= N) return;

    int start = __ldg(rowptr + w);
    int end   = __ldg(rowptr + w + 1);

    float ax = 0.0f, ay = 0.0f;
    for (int base = start; base < end; base += 32) {
        int rem = end - base;
        int idx = 0;
        if (lane < rem) {
            idx = __ldg(perm + base + lane);
            if (remap) idx = __ldg(remap + idx);
        }
        int m = rem < 32 ? rem : 32;
        for (int j = 0; j < m; j++) {
            int s2 = __shfl_sync(0xffffffffu, idx, j);
            float2 v = *reinterpret_cast<const float2*>(xsrc + (size_t)s2 * D + lane * 2);
            ax += v.x;
            ay += v.y;
        }
    }

    int deg = end - start;
    float inv = (deg > 0) ? (1.0f / (float)deg) : 0.0f;
    float2 o;
    o.x = ax * inv;
    o.y = ay * inv;
    *reinterpret_cast<float2*>(outm + (size_t)w * D + lane * 2) = o;
}

// ---------------------------------------------------------------------------
// Post GEMM with packed fma.rn.f32x2:
//   out[128-row tile, 64 cols] = L2norm_rows([agg|x](128x128) @ [Wl;Wr](128x64) + b)
// 256 threads: tx = tid&15 (4 cols), ty = tid>>4 (8 rows = 4 row-pairs).
// A row-pairs come packed for free from shared (ld.shared.v4 -> 2x b64);
// W scalars are lane-duplicated via mov.b64 (ALU pipe, overlaps FMA issue).
// ---------------------------------------------------------------------------
#define KP 132   // sIn pitch (floats): 128 rows + pad
#define WPP 68   // sW pitch (floats): 64 cols + pad

__global__ void __launch_bounds__(256)
sage_post_gemm(const float* __restrict__ acc,
               const float* __restrict__ xdst_base,
               const int*   __restrict__ remap,
               const float* __restrict__ Wl,
               const float* __restrict__ bl,
               const float* __restrict__ Wr,
               float* __restrict__ out,
               int N, int relu)
{
    extern __shared__ float sh[];
    float* sIn = sh;                 // [128 k][KP rows]
    float* sW  = sh + 128 * KP;      // [128 k][WPP cols]

    const int tid = threadIdx.x;
    const int r0 = blockIdx.x * 128;

    // ---- Stage weights ----
    #pragma unroll
    for (int p = 0; p < 8; p++) {
        int i = tid + p * 256;          // f4 idx 0..2047
        int k = i >> 4;
        int c = (i & 15) << 2;
        float4 w = (k < 64)
            ? *reinterpret_cast<const float4*>(Wl + k * D + c)
            : *reinterpret_cast<const float4*>(Wr + (k - 64) * D + c);
        *reinterpret_cast<float4*>(&sW[k * WPP + c]) = w;
    }

    // ---- Stage input tile k-major: half 0 -> agg rows (k 0..63),
    //      half 1 -> x rows (k 64..127) ----
    {
        int row  = tid & 127;
        int half = tid >> 7;
        int gr   = r0 + row;
        bool ok  = (gr < N);
        const float* p;
        if (half == 0) {
            p = acc + (size_t)(ok ? gr : 0) * D;
        } else {
            int xr = ok ? (remap ? __ldg(remap + gr) : gr) : 0;
            p = xdst_base + (size_t)xr * D;
        }
        int kbase = half * 64;
        #pragma unroll
        for (int j = 0; j < 16; j++) {
            float4 v = ok ? reinterpret_cast<const float4*>(p)[j]
                          : make_float4(0.f, 0.f, 0.f, 0.f);
            int k = kbase + j * 4;
            sIn[(k + 0) * KP + row] = v.x;
            sIn[(k + 1) * KP + row] = v.y;
            sIn[(k + 2) * KP + row] = v.z;
            sIn[(k + 3) * KP + row] = v.w;
        }
    }
    __syncthreads();

    const int tx = tid & 15;
    const int ty = tid >> 4;

    // Accumulators: o[pr][c] holds rows (ty*8+2pr, ty*8+2pr+1) at col tx*4+c
    unsigned long long o[4][4];
    {
        float4 b4 = *reinterpret_cast<const float4*>(bl + tx * 4);
        unsigned long long b0, b1, b2, b3;
        PACK2(b0, b4.x, b4.x); PACK2(b1, b4.y, b4.y);
        PACK2(b2, b4.z, b4.z); PACK2(b3, b4.w, b4.w);
        #pragma unroll
        for (int pr = 0; pr < 4; pr++) {
            o[pr][0] = b0; o[pr][1] = b1; o[pr][2] = b2; o[pr][3] = b3;
        }
    }

    const float* aPtr = sIn + ty * 8;
    const float* wPtr = sW + tx * 4;

    #pragma unroll 8
    for (int k = 0; k < 128; k++) {
        ulonglong2 A0 = *reinterpret_cast<const ulonglong2*>(aPtr + k * KP);      // pairs (r0,r1),(r2,r3)
        ulonglong2 A1 = *reinterpret_cast<const ulonglong2*>(aPtr + k * KP + 4);  // pairs (r4,r5),(r6,r7)
        float4 w = *reinterpret_cast<const float4*>(wPtr + k * WPP);
        unsigned long long w0, w1, w2, w3;
        PACK2(w0, w.x, w.x); PACK2(w1, w.y, w.y);
        PACK2(w2, w.z, w.z); PACK2(w3, w.w, w.w);

        FMA2(o[0][0], A0.x, w0); FMA2(o[0][1], A0.x, w1);
        FMA2(o[0][2], A0.x, w2); FMA2(o[0][3], A0.x, w3);
        FMA2(o[1][0], A0.y, w0); FMA2(o[1][1], A0.y, w1);
        FMA2(o[1][2], A0.y, w2); FMA2(o[1][3], A0.y, w3);
        FMA2(o[2][0], A1.x, w0); FMA2(o[2][1], A1.x, w1);
        FMA2(o[2][2], A1.x, w2); FMA2(o[2][3], A1.x, w3);
        FMA2(o[3][0], A1.y, w0); FMA2(o[3][1], A1.y, w1);
        FMA2(o[3][2], A1.y, w2); FMA2(o[3][3], A1.y, w3);
    }

    // ---- Row-pair sum of squares (packed), then cross-tx reduction ----
    float ssl[4], ssh[4];
    #pragma unroll
    for (int pr = 0; pr < 4; pr++) {
        unsigned long long s2;
        PACK2(s2, 0.0f, 0.0f);
        FMA2(s2, o[pr][0], o[pr][0]);
        FMA2(s2, o[pr][1], o[pr][1]);
        FMA2(s2, o[pr][2], o[pr][2]);
        FMA2(s2, o[pr][3], o[pr][3]);
        UNPACK2(ssl[pr], ssh[pr], s2);
    }
    #pragma unroll
    for (int m = 1; m <= 8; m <<= 1) {
        #pragma unroll
        for (int pr = 0; pr < 4; pr++) {
            ssl[pr] += __shfl_xor_sync(0xffffffffu, ssl[pr], m);
            ssh[pr] += __shfl_xor_sync(0xffffffffu, ssh[pr], m);
        }
    }

    // ---- Normalize (+ReLU) and store ----
    #pragma unroll
    for (int pr = 0; pr < 4; pr++) {
        float c0l, c0h, c1l, c1h, c2l, c2h, c3l, c3h;
        UNPACK2(c0l, c0h, o[pr][0]);
        UNPACK2(c1l, c1h, o[pr][1]);
        UNPACK2(c2l, c2h, o[pr][2]);
        UNPACK2(c3l, c3h, o[pr][3]);

        int grl = r0 + ty * 8 + pr * 2;
        if (grl < N) {
            float inv = 1.0f / fmaxf(sqrtf(ssl[pr]), 1e-12f);
            float4 v = make_float4(c0l * inv, c1l * inv, c2l * inv, c3l * inv);
            if (relu) {
                v.x = fmaxf(v.x, 0.f); v.y = fmaxf(v.y, 0.f);
                v.z = fmaxf(v.z, 0.f); v.w = fmaxf(v.w, 0.f);
            }
            *reinterpret_cast<float4*>(out + (size_t)grl * D + tx * 4) = v;
        }
        int grh = grl + 1;
        if (grh < N) {
            float inv = 1.0f / fmaxf(sqrtf(ssh[pr]), 1e-12f);
            float4 v = make_float4(c0h * inv, c1h * inv, c2h * inv, c3h * inv);
            if (relu) {
                v.x = fmaxf(v.x, 0.f); v.y = fmaxf(v.y, 0.f);
                v.z = fmaxf(v.z, 0.f); v.w = fmaxf(v.w, 0.f);
            }
            *reinterpret_cast<float4*>(out + (size_t)grh * D + tx * 4) = v;
        }
    }
}

// ---------------------------------------------------------------------------
// Launch
// ---------------------------------------------------------------------------
extern "C" void kernel_launch(void* const* d_in, const int* in_sizes, int n_in,
                              void* d_out, int out_size)
{
    const float* emb_user = (const float*)d_in[0];
    const float* emb_item = (const float*)d_in[1];
    const float* W1l_ui = (const float*)d_in[2];
    const float* b1_ui  = (const float*)d_in[3];
    const float* W1r_ui = (const float*)d_in[4];
    const float* W1l_iu = (const float*)d_in[5];
    const float* b1_iu  = (const float*)d_in[6];
    const float* W1r_iu = (const float*)d_in[7];
    const float* W2l_ui = (const float*)d_in[8];
    const float* b2_ui  = (const float*)d_in[9];
    const float* W2r_ui = (const float*)d_in[10];
    const float* W2l_iu = (const float*)d_in[11];
    const float* b2_iu  = (const float*)d_in[12];
    const float* W2r_iu = (const float*)d_in[13];
    const int* n_id_user = (const int*)d_in[14];
    const int* n_id_item = (const int*)d_in[15];
    const int* edge_ui   = (const int*)d_in[16];
    const int* edge_iu   = (const int*)d_in[17];

    const int E_ui = in_sizes[16] / 2;
    const int E_iu = in_sizes[17] / 2;

    float* out = (float*)d_out;
    float* out_user = out;
    float* out_item = out + (size_t)NU * D;

    float *acc_i, *acc_u, *h_i, *h_u;
    int *deg_i, *deg_u, *rp_i, *rp_u, *cur_i, *cur_u, *perm_ui, *perm_iu, *bsum, *boff;
    cudaGetSymbolAddress((void**)&acc_i, g_acc_i);
    cudaGetSymbolAddress((void**)&acc_u, g_acc_u);
    cudaGetSymbolAddress((void**)&h_i, g_h_i);
    cudaGetSymbolAddress((void**)&h_u, g_h_u);
    cudaGetSymbolAddress((void**)&deg_i, g_deg_i);
    cudaGetSymbolAddress((void**)&deg_u, g_deg_u);
    cudaGetSymbolAddress((void**)&rp_i, g_rp_i);
    cudaGetSymbolAddress((void**)&rp_u, g_rp_u);
    cudaGetSymbolAddress((void**)&cur_i, g_cur_i);
    cudaGetSymbolAddress((void**)&cur_u, g_cur_u);
    cudaGetSymbolAddress((void**)&perm_ui, g_perm_ui);
    cudaGetSymbolAddress((void**)&perm_iu, g_perm_iu);
    cudaGetSymbolAddress((void**)&bsum, g_bsum);
    cudaGetSymbolAddress((void**)&boff, g_boff);

    const int TPB = 256;
    const int eBlocksUI = (E_ui + TPB - 1) / TPB;
    const int eBlocksIU = (E_iu + TPB - 1) / TPB;
    const int aggBlocksI = (NI * 32 + TPB - 1) / TPB;
    const int aggBlocksU = (NU * 32 + TPB - 1) / TPB;
    const int postBlocksI = (NI + 127) / 128;
    const int postBlocksU = (NU + 127) / 128;
    const int postSmem = (128 * KP + 128 * WPP) * (int)sizeof(float);  // 102400 B

    cudaFuncSetAttribute(sage_post_gemm,
                         cudaFuncAttributeMaxDynamicSharedMemorySize, postSmem);

    // ---- CSR build ----
    cudaMemsetAsync(deg_i, 0, NI * sizeof(int));
    cudaMemsetAsync(deg_u, 0, NU * sizeof(int));

    hist_k<<<eBlocksUI, TPB>>>(edge_ui + E_ui, E_ui, deg_i);
    hist_k<<<eBlocksIU, TPB>>>(edge_iu + E_iu, E_iu, deg_u);

    scanA_k<<<NB_I, 256>>>(deg_i, NI, bsum);
    scanB_k<<<1, 1024>>>(bsum, NB_I, boff, rp_i, NI);
    scanC_k<<<NB_I, 256>>>(deg_i, NI, boff, rp_i, cur_i);
    permute_k<<<eBlocksUI, TPB>>>(edge_ui, E_ui, cur_i, perm_ui);

    scanA_k<<<NB_U, 256>>>(deg_u, NU, bsum);
    scanB_k<<<1, 1024>>>(bsum, NB_U, boff, rp_u, NU);
    scanC_k<<<NB_U, 256>>>(deg_u, NU, boff, rp_u, cur_u);
    permute_k<<<eBlocksIU, TPB>>>(edge_iu, E_iu, cur_u, perm_iu);

    // ---- Layer 1 ----
    agg_k<<<aggBlocksI, TPB>>>(emb_user, n_id_user, rp_i, perm_ui, acc_i, NI);
    agg_k<<<aggBlocksU, TPB>>>(emb_item, n_id_item, rp_u, perm_iu, acc_u, NU);

    sage_post_gemm<<<postBlocksI, TPB, postSmem>>>(acc_i, emb_item, n_id_item,
                                                   W1l_ui, b1_ui, W1r_ui, h_i, NI, 1);
    sage_post_gemm<<<postBlocksU, TPB, postSmem>>>(acc_u, emb_user, n_id_user,
                                                   W1l_iu, b1_iu, W1r_iu, h_u, NU, 1);

    // ---- Layer 2 (same CSR) ----
    agg_k<<<aggBlocksI, TPB>>>(h_u, nullptr, rp_i, perm_ui, acc_i, NI);
    agg_k<<<aggBlocksU, TPB>>>(h_i, nullptr, rp_u, perm_iu, acc_u, NU);

    sage_post_gemm<<<postBlocksI, TPB, postSmem>>>(acc_i, h_i, nullptr,
                                                   W2l_ui, b2_ui, W2r_ui, out_item, NI, 0);
    sage_post_gemm<<<postBlocksU, TPB, postSmem>>>(acc_u, h_u, nullptr,
                                                   W2l_iu, b2_iu, W2r_iu, out_user, NU, 0);
}

// round 6
// speedup vs baseline: 2.6627x; 1.0715x over previous
#include <cuda_runtime.h>
#include <cuda_bf16.h>
#include <cstdint>

#define NU 200000
#define NI 200000
#define D  64
#define MAXE 2000000
#define NB_I ((NI + 255) / 256)
#define NB_U ((NU + 255) / 256)

// ---------------------------------------------------------------------------
// Device scratch (no cudaMalloc allowed)
// ---------------------------------------------------------------------------
__device__ float g_acc_i[(size_t)NI * D];
__device__ float g_acc_u[(size_t)NU * D];
__device__ float g_h_i[(size_t)NI * D];
__device__ float g_h_u[(size_t)NU * D];
__device__ int g_deg_i[NI];
__device__ int g_deg_u[NU];
__device__ int g_rp_i[NI + 1];
__device__ int g_rp_u[NU + 1];
__device__ int g_cur_i[NI];
__device__ int g_cur_u[NU];
__device__ int g_perm_ui[MAXE];
__device__ int g_perm_iu[MAXE];
__device__ int g_bsum[1024];
__device__ int g_boff[1024];

__device__ __forceinline__ uint32_t smem_to_u32(const void* p) {
    uint32_t a;
    asm("{ .reg .u64 t; cvta.to.shared.u64 t, %1; cvt.u32.u64 %0, t; }"
        : "=r"(a) : "l"(p));
    return a;
}

// ---------------------------------------------------------------------------
// CSR build
// ---------------------------------------------------------------------------
__global__ void hist_k(const int* __restrict__ dst, int E, int* __restrict__ deg)
{
    int i = blockIdx.x * blockDim.x + threadIdx.x;
    if (i < E) atomicAdd(&deg[__ldg(dst + i)], 1);
}

__global__ void scanA_k(const int* __restrict__ deg, int N, int* __restrict__ bsum)
{
    __shared__ int s[256];
    int tid = threadIdx.x;
    int i = blockIdx.x * 256 + tid;
    s[tid] = (i < N) ? deg[i] : 0;
    __syncthreads();
    #pragma unroll
    for (int o = 128; o; o >>= 1) {
        if (tid < o) s[tid] += s[tid + o];
        __syncthreads();
    }
    if (tid == 0) bsum[blockIdx.x] = s[0];
}

__global__ void scanB_k(const int* __restrict__ bsum, int NB,
                        int* __restrict__ boff, int* __restrict__ rowptr, int N)
{
    __shared__ int s[1024];
    int tid = threadIdx.x;
    int v = (tid < NB) ? bsum[tid] : 0;
    s[tid] = v;
    __syncthreads();
    for (int o = 1; o < 1024; o <<= 1) {
        int t = (tid >= o) ? s[tid - o] : 0;
        __syncthreads();
        s[tid] += t;
        __syncthreads();
    }
    if (tid < NB) boff[tid] = s[tid] - v;
    if (tid == NB - 1) rowptr[N] = s[tid];
}

__global__ void scanC_k(const int* __restrict__ deg, int N,
                        const int* __restrict__ boff,
                        int* __restrict__ rowptr, int* __restrict__ cursor)
{
    __shared__ int s[256];
    int tid = threadIdx.x;
    int i = blockIdx.x * 256 + tid;
    int v = (i < N) ? deg[i] : 0;
    s[tid] = v;
    __syncthreads();
    #pragma unroll
    for (int o = 1; o < 256; o <<= 1) {
        int t = (tid >= o) ? s[tid - o] : 0;
        __syncthreads();
        s[tid] += t;
        __syncthreads();
    }
    if (i < N) {
        int ex = boff[blockIdx.x] + s[tid] - v;
        rowptr[i] = ex;
        cursor[i] = ex;
    }
}

__global__ void permute_k(const int* __restrict__ edge, int E,
                          int* __restrict__ cursor, int* __restrict__ perm)
{
    int i = blockIdx.x * blockDim.x + threadIdx.x;
    if (i < E) {
        int s = __ldg(edge + i);
        int d = __ldg(edge + E + i);
        int slot = atomicAdd(&cursor[d], 1);
        perm[slot] = s;
    }
}

// ---------------------------------------------------------------------------
// Gather-side aggregation (mean). One warp per dst row.
// ---------------------------------------------------------------------------
__global__ void __launch_bounds__(256)
agg_k(const float* __restrict__ xsrc,
      const int*   __restrict__ remap,
      const int*   __restrict__ rowptr,
      const int*   __restrict__ perm,
      float* __restrict__ outm,
      int N)
{
    int w = (blockIdx.x * blockDim.x + threadIdx.x) >> 5;
    int lane = threadIdx.x & 31;
    if (w >= N) return;

    int start = __ldg(rowptr + w);
    int end   = __ldg(rowptr + w + 1);

    float ax = 0.0f, ay = 0.0f;
    for (int base = start; base < end; base += 32) {
        int rem = end - base;
        int idx = 0;
        if (lane < rem) {
            idx = __ldg(perm + base + lane);
            if (remap) idx = __ldg(remap + idx);
        }
        int m = rem < 32 ? rem : 32;
        for (int j = 0; j < m; j++) {
            int s2 = __shfl_sync(0xffffffffu, idx, j);
            float2 v = *reinterpret_cast<const float2*>(xsrc + (size_t)s2 * D + lane * 2);
            ax += v.x;
            ay += v.y;
        }
    }

    int deg = end - start;
    float inv = (deg > 0) ? (1.0f / (float)deg) : 0.0f;
    float2 o;
    o.x = ax * inv;
    o.y = ay * inv;
    *reinterpret_cast<float2*>(outm + (size_t)w * D + lane * 2) = o;
}

// ---------------------------------------------------------------------------
// Post GEMM on tensor cores via mma.sync m16n8k16 bf16 (sm_80 ISA, works on
// compute_103), with bf16-split fp32 emulation (3 accumulation passes):
//   D = A_hi*B_hi + A_lo*B_hi + A_hi*B_lo   (dropped term ~2^-16 rel)
// Tile: 128 rows x 64 cols per 256-thread block; warp w -> rows w*16..w*16+15.
// SMEM layout (bf16, pitch 136 elem = 272 B, 16B-aligned rows):
//   A_hi [128][136], A_lo [128][136]  (k-major rows: k0..63 = agg, 64..127 = x)
//   B_hi [64][136],  B_lo [64][136]   (B[n][k] = W^T)
//   bias [64] f32
// ---------------------------------------------------------------------------
#define PKB 272                   // pitch bytes
#define SM_AHI  0
#define SM_ALO  (128 * PKB)       // 34816
#define SM_BHI  (2 * 128 * PKB)   // 69632
#define SM_BLO  (SM_BHI + 64 * PKB)
#define SM_BIAS (SM_BHI + 2 * 64 * PKB)
#define POST_SMEM (SM_BIAS + 256)

#define LDMATRIX_X4(r0, r1, r2, r3, addr) \
    asm volatile("ldmatrix.sync.aligned.m8n8.x4.shared.b16 {%0, %1, %2, %3}, [%4];" \
                 : "=r"(r0), "=r"(r1), "=r"(r2), "=r"(r3) : "r"(addr))

#define MMA_BF16(d, a0, a1, a2, a3, b0, b1) \
    asm volatile("mma.sync.aligned.m16n8k16.row.col.f32.bf16.bf16.f32 " \
                 "{%0, %1, %2, %3}, {%4, %5, %6, %7}, {%8, %9}, {%0, %1, %2, %3};" \
                 : "+f"((d)[0]), "+f"((d)[1]), "+f"((d)[2]), "+f"((d)[3]) \
                 : "r"(a0), "r"(a1), "r"(a2), "r"(a3), "r"(b0), "r"(b1))

__device__ __forceinline__ uint32_t bf2u(__nv_bfloat162 v) {
    return *reinterpret_cast<uint32_t*>(&v);
}

__global__ void __launch_bounds__(256)
sage_post_tc(const float* __restrict__ acc,
             const float* __restrict__ xdst_base,
             const int*   __restrict__ remap,
             const float* __restrict__ Wl,
             const float* __restrict__ bl,
             const float* __restrict__ Wr,
             float* __restrict__ out,
             int N, int relu)
{
    extern __shared__ char smem[];
    uint32_t sb = smem_to_u32(smem);
    const int tid = threadIdx.x;
    const int warp = tid >> 5;
    const int lane = tid & 31;
    const int r0 = blockIdx.x * 128;

    // ---- Stage A: row = tid&127, half = tid>>7 (0: agg k0..63, 1: x k64..127)
    {
        int row  = tid & 127;
        int half = tid >> 7;
        int gr   = r0 + row;
        bool ok  = (gr < N);
        const float* p;
        if (half == 0) {
            p = acc + (size_t)(ok ? gr : 0) * D;
        } else {
            int xr = ok ? (remap ? __ldg(remap + gr) : gr) : 0;
            p = xdst_base + (size_t)xr * D;
        }
        char* aHiRow = smem + SM_AHI + row * PKB + half * 128;
        char* aLoRow = smem + SM_ALO + row * PKB + half * 128;
        #pragma unroll
        for (int j = 0; j < 8; j++) {       // 8 k per iter
            float4 v0 = ok ? reinterpret_cast<const float4*>(p)[j * 2]
                           : make_float4(0.f, 0.f, 0.f, 0.f);
            float4 v1 = ok ? reinterpret_cast<const float4*>(p)[j * 2 + 1]
                           : make_float4(0.f, 0.f, 0.f, 0.f);
            __nv_bfloat162 h0 = __float22bfloat162_rn(make_float2(v0.x, v0.y));
            __nv_bfloat162 h1 = __float22bfloat162_rn(make_float2(v0.z, v0.w));
            __nv_bfloat162 h2 = __float22bfloat162_rn(make_float2(v1.x, v1.y));
            __nv_bfloat162 h3 = __float22bfloat162_rn(make_float2(v1.z, v1.w));
            float2 f0 = __bfloat1622float2(h0);
            float2 f1 = __bfloat1622float2(h1);
            float2 f2 = __bfloat1622float2(h2);
            float2 f3 = __bfloat1622float2(h3);
            __nv_bfloat162 l0 = __float22bfloat162_rn(make_float2(v0.x - f0.x, v0.y - f0.y));
            __nv_bfloat162 l1 = __float22bfloat162_rn(make_float2(v0.z - f1.x, v0.w - f1.y));
            __nv_bfloat162 l2 = __float22bfloat162_rn(make_float2(v1.x - f2.x, v1.y - f2.y));
            __nv_bfloat162 l3 = __float22bfloat162_rn(make_float2(v1.z - f3.x, v1.w - f3.y));
            *reinterpret_cast<uint4*>(aHiRow + j * 16) =
                make_uint4(bf2u(h0), bf2u(h1), bf2u(h2), bf2u(h3));
            *reinterpret_cast<uint4*>(aLoRow + j * 16) =
                make_uint4(bf2u(l0), bf2u(l1), bf2u(l2), bf2u(l3));
        }
    }

    // ---- Stage B = W^T (coalesced W reads, transposed scalar STS) ----
    #pragma unroll
    for (int pp = 0; pp < 8; pp++) {
        int i = tid + pp * 256;             // f4 idx 0..2047 over [128k][16 c-groups]
        int k = i >> 4;
        int c = (i & 15) << 2;
        float4 w = (k < 64)
            ? *reinterpret_cast<const float4*>(Wl + k * D + c)
            : *reinterpret_cast<const float4*>(Wr + (k - 64) * D + c);
        float wv[4] = { w.x, w.y, w.z, w.w };
        #pragma unroll
        for (int j = 0; j < 4; j++) {
            __nv_bfloat16 hi = __float2bfloat16(wv[j]);
            __nv_bfloat16 lo = __float2bfloat16(wv[j] - __bfloat162float(hi));
            int n = c + j;
            *reinterpret_cast<__nv_bfloat16*>(smem + SM_BHI + n * PKB + k * 2) = hi;
            *reinterpret_cast<__nv_bfloat16*>(smem + SM_BLO + n * PKB + k * 2) = lo;
        }
    }
    if (tid < 64) *reinterpret_cast<float*>(smem + SM_BIAS + tid * 4) = bl[tid];
    __syncthreads();

    // ---- MMA mainloop: 3 passes x 8 k-steps, 8 n-tiles ----
    float d[8][4];
    #pragma unroll
    for (int t = 0; t < 8; t++) {
        d[t][0] = 0.f; d[t][1] = 0.f; d[t][2] = 0.f; d[t][3] = 0.f;
    }

    // ldmatrix lane address: row = warp*16 + (lane&15), k byte = (lane>>4)*16
    const uint32_t aRowOff = (uint32_t)(warp * 16 + (lane & 15)) * PKB
                           + (uint32_t)(lane >> 4) * 16;
    const uint32_t bRowOff = (uint32_t)(lane >> 2) * PKB + (uint32_t)(lane & 3) * 4;

    #pragma unroll
    for (int pass = 0; pass < 3; pass++) {
        uint32_t aBase = sb + (pass == 1 ? SM_ALO : SM_AHI) + aRowOff;
        uint32_t bBase = sb + (pass == 2 ? SM_BLO : SM_BHI) + bRowOff;
        #pragma unroll
        for (int ks = 0; ks < 8; ks++) {
            uint32_t a0, a1, a2, a3;
            LDMATRIX_X4(a0, a1, a2, a3, aBase + ks * 32);
            #pragma unroll
            for (int t = 0; t < 8; t++) {
                uint32_t b0 = *reinterpret_cast<const uint32_t*>(
                    (const char*)smem + (bBase - sb) + t * 8 * PKB + ks * 32);
                uint32_t b1 = *reinterpret_cast<const uint32_t*>(
                    (const char*)smem + (bBase - sb) + t * 8 * PKB + ks * 32 + 16);
                MMA_BF16(d[t], a0, a1, a2, a3, b0, b1);
            }
        }
    }

    // ---- Epilogue: bias, row L2 norm (4-lane groups), relu, store ----
    const float* bias = reinterpret_cast<const float*>(smem + SM_BIAS);
    int cBase = (lane & 3) * 2;
    float ssl = 0.f, ssh = 0.f;
    #pragma unroll
    for (int t = 0; t < 8; t++) {
        int c = t * 8 + cBase;
        float b0 = bias[c], b1 = bias[c + 1];
        d[t][0] += b0; d[t][1] += b1;
        d[t][2] += b0; d[t][3] += b1;
        ssl = fmaf(d[t][0], d[t][0], ssl); ssl = fmaf(d[t][1], d[t][1], ssl);
        ssh = fmaf(d[t][2], d[t][2], ssh); ssh = fmaf(d[t][3], d[t][3], ssh);
    }
    ssl += __shfl_xor_sync(0xffffffffu, ssl, 1);
    ssl += __shfl_xor_sync(0xffffffffu, ssl, 2);
    ssh += __shfl_xor_sync(0xffffffffu, ssh, 1);
    ssh += __shfl_xor_sync(0xffffffffu, ssh, 2);

    int rlo = r0 + warp * 16 + (lane >> 2);
    int rhi = rlo + 8;
    float invl = 1.0f / fmaxf(sqrtf(ssl), 1e-12f);
    float invh = 1.0f / fmaxf(sqrtf(ssh), 1e-12f);

    if (rlo < N) {
        float* op = out + (size_t)rlo * D + cBase;
        #pragma unroll
        for (int t = 0; t < 8; t++) {
            float2 v = make_float2(d[t][0] * invl, d[t][1] * invl);
            if (relu) { v.x = fmaxf(v.x, 0.f); v.y = fmaxf(v.y, 0.f); }
            *reinterpret_cast<float2*>(op + t * 8) = v;
        }
    }
    if (rhi < N) {
        float* op = out + (size_t)rhi * D + cBase;
        #pragma unroll
        for (int t = 0; t < 8; t++) {
            float2 v = make_float2(d[t][2] * invh, d[t][3] * invh);
            if (relu) { v.x = fmaxf(v.x, 0.f); v.y = fmaxf(v.y, 0.f); }
            *reinterpret_cast<float2*>(op + t * 8) = v;
        }
    }
}

// ---------------------------------------------------------------------------
// Launch
// ---------------------------------------------------------------------------
extern "C" void kernel_launch(void* const* d_in, const int* in_sizes, int n_in,
                              void* d_out, int out_size)
{
    const float* emb_user = (const float*)d_in[0];
    const float* emb_item = (const float*)d_in[1];
    const float* W1l_ui = (const float*)d_in[2];
    const float* b1_ui  = (const float*)d_in[3];
    const float* W1r_ui = (const float*)d_in[4];
    const float* W1l_iu = (const float*)d_in[5];
    const float* b1_iu  = (const float*)d_in[6];
    const float* W1r_iu = (const float*)d_in[7];
    const float* W2l_ui = (const float*)d_in[8];
    const float* b2_ui  = (const float*)d_in[9];
    const float* W2r_ui = (const float*)d_in[10];
    const float* W2l_iu = (const float*)d_in[11];
    const float* b2_iu  = (const float*)d_in[12];
    const float* W2r_iu = (const float*)d_in[13];
    const int* n_id_user = (const int*)d_in[14];
    const int* n_id_item = (const int*)d_in[15];
    const int* edge_ui   = (const int*)d_in[16];
    const int* edge_iu   = (const int*)d_in[17];

    const int E_ui = in_sizes[16] / 2;
    const int E_iu = in_sizes[17] / 2;

    float* out = (float*)d_out;
    float* out_user = out;
    float* out_item = out + (size_t)NU * D;

    float *acc_i, *acc_u, *h_i, *h_u;
    int *deg_i, *deg_u, *rp_i, *rp_u, *cur_i, *cur_u, *perm_ui, *perm_iu, *bsum, *boff;
    cudaGetSymbolAddress((void**)&acc_i, g_acc_i);
    cudaGetSymbolAddress((void**)&acc_u, g_acc_u);
    cudaGetSymbolAddress((void**)&h_i, g_h_i);
    cudaGetSymbolAddress((void**)&h_u, g_h_u);
    cudaGetSymbolAddress((void**)&deg_i, g_deg_i);
    cudaGetSymbolAddress((void**)&deg_u, g_deg_u);
    cudaGetSymbolAddress((void**)&rp_i, g_rp_i);
    cudaGetSymbolAddress((void**)&rp_u, g_rp_u);
    cudaGetSymbolAddress((void**)&cur_i, g_cur_i);
    cudaGetSymbolAddress((void**)&cur_u, g_cur_u);
    cudaGetSymbolAddress((void**)&perm_ui, g_perm_ui);
    cudaGetSymbolAddress((void**)&perm_iu, g_perm_iu);
    cudaGetSymbolAddress((void**)&bsum, g_bsum);
    cudaGetSymbolAddress((void**)&boff, g_boff);

    const int TPB = 256;
    const int eBlocksUI = (E_ui + TPB - 1) / TPB;
    const int eBlocksIU = (E_iu + TPB - 1) / TPB;
    const int aggBlocksI = (NI * 32 + TPB - 1) / TPB;
    const int aggBlocksU = (NU * 32 + TPB - 1) / TPB;
    const int postBlocksI = (NI + 127) / 128;
    const int postBlocksU = (NU + 127) / 128;

    cudaFuncSetAttribute(sage_post_tc,
                         cudaFuncAttributeMaxDynamicSharedMemorySize, POST_SMEM);

    // ---- CSR build ----
    cudaMemsetAsync(deg_i, 0, NI * sizeof(int));
    cudaMemsetAsync(deg_u, 0, NU * sizeof(int));

    hist_k<<<eBlocksUI, TPB>>>(edge_ui + E_ui, E_ui, deg_i);
    hist_k<<<eBlocksIU, TPB>>>(edge_iu + E_iu, E_iu, deg_u);

    scanA_k<<<NB_I, 256>>>(deg_i, NI, bsum);
    scanB_k<<<1, 1024>>>(bsum, NB_I, boff, rp_i, NI);
    scanC_k<<<NB_I, 256>>>(deg_i, NI, boff, rp_i, cur_i);
    permute_k<<<eBlocksUI, TPB>>>(edge_ui, E_ui, cur_i, perm_ui);

    scanA_k<<<NB_U, 256>>>(deg_u, NU, bsum);
    scanB_k<<<1, 1024>>>(bsum, NB_U, boff, rp_u, NU);
    scanC_k<<<NB_U, 256>>>(deg_u, NU, boff, rp_u, cur_u);
    permute_k<<<eBlocksIU, TPB>>>(edge_iu, E_iu, cur_u, perm_iu);

    // ---- Layer 1 ----
    agg_k<<<aggBlocksI, TPB>>>(emb_user, n_id_user, rp_i, perm_ui, acc_i, NI);
    agg_k<<<aggBlocksU, TPB>>>(emb_item, n_id_item, rp_u, perm_iu, acc_u, NU);

    sage_post_tc<<<postBlocksI, TPB, POST_SMEM>>>(acc_i, emb_item, n_id_item,
                                                  W1l_ui, b1_ui, W1r_ui, h_i, NI, 1);
    sage_post_tc<<<postBlocksU, TPB, POST_SMEM>>>(acc_u, emb_user, n_id_user,
                                                  W1l_iu, b1_iu, W1r_iu, h_u, NU, 1);

    // ---- Layer 2 (same CSR) ----
    agg_k<<<aggBlocksI, TPB>>>(h_u, nullptr, rp_i, perm_ui, acc_i, NI);
    agg_k<<<aggBlocksU, TPB>>>(h_i, nullptr, rp_u, perm_iu, acc_u, NU);

    sage_post_tc<<<postBlocksI, TPB, POST_SMEM>>>(acc_i, h_i, nullptr,
                                                  W2l_ui, b2_ui, W2r_ui, out_item, NI, 0);
    sage_post_tc<<<postBlocksU, TPB, POST_SMEM>>>(acc_u, h_u, nullptr,
                                                  W2l_iu, b2_iu, W2r_iu, out_user, NU, 0);
}